// round 1
// baseline (speedup 1.0000x reference)
#include <cuda_runtime.h>

// ---------------- problem dims ----------------
#define NPTS   4096
#define HDIM   64
#define ODIM   16
#define JSPLIT 8
#define TJ     128
#define JRANGE (NPTS / JSPLIT)

typedef unsigned long long ull;

// ---------------- f32x2 helpers (Blackwell packed fp32) ----------------
static __device__ __forceinline__ ull pk(float a, float b) {
    ull r; asm("mov.b64 %0, {%1, %2};" : "=l"(r) : "f"(a), "f"(b)); return r;
}
static __device__ __forceinline__ void upk(ull x, float& a, float& b) {
    asm("mov.b64 {%0, %1}, %2;" : "=f"(a), "=f"(b) : "l"(x));
}
static __device__ __forceinline__ ull fma2(ull a, ull b, ull c) {
    ull d; asm("fma.rn.f32x2 %0, %1, %2, %3;" : "=l"(d) : "l"(a), "l"(b), "l"(c)); return d;
}
static __device__ __forceinline__ ull mul2(ull a, ull b) {
    ull d; asm("mul.rn.f32x2 %0, %1, %2;" : "=l"(d) : "l"(a), "l"(b)); return d;
}
static __device__ __forceinline__ float leaky(float x) { return fmaxf(x, 0.2f * x); }

static __device__ __forceinline__ float warp_sum(float v) {
    #pragma unroll
    for (int o = 16; o; o >>= 1) v += __shfl_down_sync(0xffffffffu, v, o);
    return v;
}

// ---------------- scratch (static device memory; no runtime allocs) ----------------
__device__ float  g_fpre[NPTS * HDIM];          // pre-norm features f
__device__ float4 g_f[NPTS * HDIM / 4];         // normalized f, [j][h]
__device__ float4 g_respart4[JSPLIT * NPTS * HDIM / 4]; // j-split partial results
__device__ float  g_opre[NPTS * ODIM];          // pre-norm output MLP
__device__ float  g_pin[32 * 8];                // per-block partial group stats (in)
__device__ float  g_pout[32 * 8];               // per-block partial group stats (out)
__device__ float2 g_statin[4];                  // (mu, rstd) per group (in)
__device__ float2 g_statout[4];                 // (mu, rstd) per group (out)

// ---------------- kernel 1: input MLP (16->64->64) + partial group stats ----------------
__global__ void k_infeat(const float* __restrict__ feat,
                         const float* __restrict__ W1, const float* __restrict__ b1,
                         const float* __restrict__ W2, const float* __restrict__ b2) {
    __shared__ float4 W1s[256];   // 64x16
    __shared__ float4 W2s[1024];  // 64x64
    __shared__ float  b1s[64], b2s[64];
    __shared__ float  red[4][8];
    int tid = threadIdx.x;
    for (int t = tid; t < 256;  t += 128) W1s[t] = ((const float4*)W1)[t];
    for (int t = tid; t < 1024; t += 128) W2s[t] = ((const float4*)W2)[t];
    if (tid < 64) { b1s[tid] = b1[tid]; b2s[tid] = b2[tid]; }
    __syncthreads();

    int p = blockIdx.x * 128 + tid;
    float f[16];
    #pragma unroll
    for (int k = 0; k < 16; k++) f[k] = feat[p * 16 + k];

    float t1[64];
    #pragma unroll
    for (int h = 0; h < 64; h++) {
        float s = b1s[h];
        #pragma unroll
        for (int k4 = 0; k4 < 4; k4++) {
            float4 w = W1s[h * 4 + k4];
            s = fmaf(w.x, f[k4*4+0], fmaf(w.y, f[k4*4+1], fmaf(w.z, f[k4*4+2], fmaf(w.w, f[k4*4+3], s))));
        }
        t1[h] = leaky(s);
    }

    float gs[4] = {0,0,0,0}, gq[4] = {0,0,0,0};
    for (int h = 0; h < 64; h++) {
        float s = b2s[h];
        #pragma unroll
        for (int k4 = 0; k4 < 16; k4++) {
            float4 w = W2s[h * 16 + k4];
            s = fmaf(w.x, t1[k4*4+0], fmaf(w.y, t1[k4*4+1], fmaf(w.z, t1[k4*4+2], fmaf(w.w, t1[k4*4+3], s))));
        }
        float v = leaky(s);
        g_fpre[p * 64 + h] = v;
        int g = h >> 4; gs[g] += v; gq[g] += v * v;
    }

    int w = tid >> 5, l = tid & 31;
    #pragma unroll
    for (int g = 0; g < 4; g++) {
        float s = warp_sum(gs[g]);
        float q = warp_sum(gq[g]);
        if (l == 0) { red[w][g*2] = s; red[w][g*2+1] = q; }
    }
    __syncthreads();
    if (tid < 8) g_pin[blockIdx.x * 8 + tid] = red[0][tid] + red[1][tid] + red[2][tid] + red[3][tid];
}

// ---------------- kernel 2/6: finalize group stats (deterministic fixed-order sum) ----------------
__global__ void k_finstat(int which) {
    int g = threadIdx.x;
    if (g < 4) {
        const float* pin = which ? g_pout : g_pin;
        float invc = which ? (1.0f / 16384.0f) : (1.0f / 65536.0f);
        float s = 0.f, q = 0.f;
        for (int b = 0; b < 32; b++) { s += pin[b*8 + g*2]; q += pin[b*8 + g*2 + 1]; }
        float mu  = s * invc;
        float var = q * invc - mu * mu;
        float2 st = make_float2(mu, rsqrtf(var + 1e-5f));
        if (which) g_statout[g] = st; else g_statin[g] = st;
    }
}

// ---------------- kernel 3: apply GroupNorm to f ----------------
__global__ void k_fnorm(const float* __restrict__ gin, const float* __restrict__ bin) {
    int idx = blockIdx.x * 256 + threadIdx.x;
    int h = idx & 63, g = h >> 4;
    float2 st = g_statin[g];
    float v = (g_fpre[idx] - st.x) * st.y;
    ((float*)g_f)[idx] = v * gin[h] + bin[h];
}

// ---------------- kernel 4: the pairwise convolution (dominant) ----------------
// Warp = 8 i's x 4 h-lanes (16 channels each). f32x2-packed A2 matvec + accumulate.
__global__ void __launch_bounds__(128) k_conv(
        const float* __restrict__ points, const float* __restrict__ nuvp,
        const float* __restrict__ A1, const float* __restrict__ B1,
        const float* __restrict__ A2, const float* __restrict__ B2) {
    __shared__ float4 sp[TJ], sn[TJ];
    __shared__ float4 sf[TJ * 16];   // f tile, [j][h/4]

    const float S = 0.70710678118654752f;  // 1/(sqrt(2)*RADIUS)
    int tid = threadIdx.x;
    int warp = tid >> 5, lane = tid & 31, isub = lane & 7, hl = lane >> 3;
    int i  = blockIdx.x * 32 + warp * 8 + isub;
    int h0 = hl * 16;

    float pix = points[3*i+0]*S, piy = points[3*i+1]*S, piz = points[3*i+2]*S;
    float nix = nuvp[9*i+0],     niy = nuvp[9*i+1],     niz = nuvp[9*i+2];

    // M = A1 @ nuv_i  (8x3), folds the local-basis projection into A1
    float M[8][3], B1r[8];
    #pragma unroll
    for (int c = 0; c < 8; c++) {
        float a0 = A1[c*3+0], a1 = A1[c*3+1], a2c = A1[c*3+2];
        #pragma unroll
        for (int d = 0; d < 3; d++)
            M[c][d] = fmaf(a0, nuvp[9*i + d], fmaf(a1, nuvp[9*i + 3 + d], a2c * nuvp[9*i + 6 + d]));
        B1r[c] = B1[c];
    }

    // A2 slice for this lane's 16 channels, packed as h-pairs: a2r[c][hp]
    ull a2r[8][8];
    #pragma unroll
    for (int hp = 0; hp < 8; hp++)
        #pragma unroll
        for (int c = 0; c < 8; c++)
            a2r[c][hp] = pk(A2[(h0 + 2*hp) * 8 + c], A2[(h0 + 2*hp + 1) * 8 + c]);
    ull b2p[8];
    #pragma unroll
    for (int hp = 0; hp < 8; hp++) b2p[hp] = pk(B2[h0 + 2*hp], B2[h0 + 2*hp + 1]);

    ull acc[8];
    #pragma unroll
    for (int hp = 0; hp < 8; hp++) acc[hp] = pk(0.f, 0.f);

    int j0base = blockIdx.y * JRANGE;
    for (int jb = 0; jb < JRANGE; jb += TJ) {
        int j0 = j0base + jb;
        __syncthreads();
        for (int t = tid; t < TJ; t += 128) {
            int j = j0 + t;
            sp[t] = make_float4(points[3*j]*S, points[3*j+1]*S, points[3*j+2]*S, 0.f);
            sn[t] = make_float4(nuvp[9*j], nuvp[9*j+1], nuvp[9*j+2], 0.f);
        }
        for (int t = tid; t < TJ * 16; t += 128) sf[t] = g_f[j0 * 16 + t];
        __syncthreads();

        #pragma unroll 1
        for (int jj = 0; jj < TJ; jj++) {
            float4 pj = sp[jj], nj = sn[jj];
            float dx = pj.x - pix, dy = pj.y - piy, dz = pj.z - piz;
            float sq = fmaf(dx, dx, fmaf(dy, dy, dz * dz));
            float dt = fmaf(nix, nj.x, fmaf(niy, nj.y, niz * nj.z));
            float t2 = 2.0f - dt;
            float w  = __expf(-sq * t2 * t2);
            ull ws = pk(w, w);

            ull ys[8];
            #pragma unroll
            for (int c = 0; c < 8; c++) {
                float y = fmaf(M[c][0], dx, fmaf(M[c][1], dy, fmaf(M[c][2], dz, B1r[c])));
                y = fmaxf(y, 0.f);
                ys[c] = pk(y, y);
            }

            const float4* frow = sf + jj * 16 + hl * 4;
            #pragma unroll
            for (int hf = 0; hf < 2; hf++) {
                ull g0 = b2p[hf*4+0], g1 = b2p[hf*4+1], g2 = b2p[hf*4+2], g3 = b2p[hf*4+3];
                #pragma unroll
                for (int c = 0; c < 8; c++) {
                    g0 = fma2(a2r[c][hf*4+0], ys[c], g0);
                    g1 = fma2(a2r[c][hf*4+1], ys[c], g1);
                    g2 = fma2(a2r[c][hf*4+2], ys[c], g2);
                    g3 = fma2(a2r[c][hf*4+3], ys[c], g3);
                }
                float4 fa = frow[hf*2+0], fb = frow[hf*2+1];
                float x0, x1;
                upk(g0, x0, x1);
                acc[hf*4+0] = fma2(mul2(pk(fmaxf(x0,0.f), fmaxf(x1,0.f)), pk(fa.x, fa.y)), ws, acc[hf*4+0]);
                upk(g1, x0, x1);
                acc[hf*4+1] = fma2(mul2(pk(fmaxf(x0,0.f), fmaxf(x1,0.f)), pk(fa.z, fa.w)), ws, acc[hf*4+1]);
                upk(g2, x0, x1);
                acc[hf*4+2] = fma2(mul2(pk(fmaxf(x0,0.f), fmaxf(x1,0.f)), pk(fb.x, fb.y)), ws, acc[hf*4+2]);
                upk(g3, x0, x1);
                acc[hf*4+3] = fma2(mul2(pk(fmaxf(x0,0.f), fmaxf(x1,0.f)), pk(fb.z, fb.w)), ws, acc[hf*4+3]);
            }
        }
    }

    float* rp = ((float*)g_respart4) + ((size_t)blockIdx.y * NPTS + i) * 64 + h0;
    #pragma unroll
    for (int hp = 0; hp < 8; hp++) {
        float a, b; upk(acc[hp], a, b);
        rp[2*hp] = a; rp[2*hp+1] = b;
    }
}

// ---------------- kernel 5: reduce j-splits + output MLP (64->16->16) + partial stats ----------------
__global__ void k_outfeat(const float* __restrict__ W1, const float* __restrict__ b1,
                          const float* __restrict__ W2, const float* __restrict__ b2) {
    __shared__ float4 W1s[256];  // 16x64
    __shared__ float4 W2s[64];   // 16x16
    __shared__ float  b1s[16], b2s[16];
    __shared__ float  red[4][8];
    int tid = threadIdx.x;
    for (int t = tid; t < 256; t += 128) W1s[t] = ((const float4*)W1)[t];
    if (tid < 64) W2s[tid] = ((const float4*)W2)[tid];
    if (tid < 16) { b1s[tid] = b1[tid]; b2s[tid] = b2[tid]; }
    __syncthreads();

    int p = blockIdx.x * 128 + tid;
    float4 r4[16];
    #pragma unroll
    for (int k = 0; k < 16; k++) r4[k] = g_respart4[(size_t)p * 16 + k];
    #pragma unroll
    for (int s = 1; s < JSPLIT; s++)
        #pragma unroll
        for (int k = 0; k < 16; k++) {
            float4 v = g_respart4[((size_t)s * NPTS + p) * 16 + k];
            r4[k].x += v.x; r4[k].y += v.y; r4[k].z += v.z; r4[k].w += v.w;
        }

    float o1[16];
    #pragma unroll
    for (int h = 0; h < 16; h++) {
        float s = b1s[h];
        #pragma unroll
        for (int k = 0; k < 16; k++) {
            float4 w = W1s[h * 16 + k]; float4 v = r4[k];
            s = fmaf(w.x, v.x, fmaf(w.y, v.y, fmaf(w.z, v.z, fmaf(w.w, v.w, s))));
        }
        o1[h] = leaky(s);
    }

    float gs[4] = {0,0,0,0}, gq[4] = {0,0,0,0};
    #pragma unroll
    for (int h = 0; h < 16; h++) {
        float s = b2s[h];
        #pragma unroll
        for (int k4 = 0; k4 < 4; k4++) {
            float4 w = W2s[h * 4 + k4];
            s = fmaf(w.x, o1[k4*4+0], fmaf(w.y, o1[k4*4+1], fmaf(w.z, o1[k4*4+2], fmaf(w.w, o1[k4*4+3], s))));
        }
        float v = leaky(s);
        g_opre[p * 16 + h] = v;
        int g = h >> 2; gs[g] += v; gq[g] += v * v;
    }

    int w = tid >> 5, l = tid & 31;
    #pragma unroll
    for (int g = 0; g < 4; g++) {
        float s = warp_sum(gs[g]);
        float q = warp_sum(gq[g]);
        if (l == 0) { red[w][g*2] = s; red[w][g*2+1] = q; }
    }
    __syncthreads();
    if (tid < 8) g_pout[blockIdx.x * 8 + tid] = red[0][tid] + red[1][tid] + red[2][tid] + red[3][tid];
}

// ---------------- kernel 7: final GroupNorm -> d_out ----------------
__global__ void k_onorm(float* __restrict__ out,
                        const float* __restrict__ gout, const float* __restrict__ bout) {
    int idx = blockIdx.x * 256 + threadIdx.x;
    int h = idx & 15, g = h >> 2;
    float2 st = g_statout[g];
    out[idx] = (g_opre[idx] - st.x) * st.y * gout[h] + bout[h];
}

// ---------------- launch ----------------
extern "C" void kernel_launch(void* const* d_in, const int* in_sizes, int n_in,
                              void* d_out, int out_size) {
    const float* points   = (const float*)d_in[0];
    const float* nuv      = (const float*)d_in[1];
    const float* features = (const float*)d_in[2];
    const float* W_in1    = (const float*)d_in[3];
    const float* b_in1    = (const float*)d_in[4];
    const float* W_in2    = (const float*)d_in[5];
    const float* b_in2    = (const float*)d_in[6];
    const float* g_in     = (const float*)d_in[7];
    const float* beta_in  = (const float*)d_in[8];
    const float* A1       = (const float*)d_in[9];
    const float* B1       = (const float*)d_in[10];
    const float* A2       = (const float*)d_in[11];
    const float* B2       = (const float*)d_in[12];
    const float* W_out1   = (const float*)d_in[13];
    const float* b_out1   = (const float*)d_in[14];
    const float* W_out2   = (const float*)d_in[15];
    const float* b_out2   = (const float*)d_in[16];
    const float* g_out    = (const float*)d_in[17];
    const float* beta_out = (const float*)d_in[18];
    float* out = (float*)d_out;

    k_infeat <<<32, 128>>>(features, W_in1, b_in1, W_in2, b_in2);
    k_finstat<<<1, 32>>>(0);
    k_fnorm  <<<NPTS * HDIM / 256, 256>>>(g_in, beta_in);
    k_conv   <<<dim3(NPTS / 32, JSPLIT), 128>>>(points, nuv, A1, B1, A2, B2);
    k_outfeat<<<32, 128>>>(W_out1, b_out1, W_out2, b_out2);
    k_finstat<<<1, 32>>>(1);
    k_onorm  <<<NPTS * ODIM / 256, 256>>>(out, g_out, beta_out);
}